// round 5
// baseline (speedup 1.0000x reference)
#include <cuda_runtime.h>
#include <cuda_bf16.h>

// CrossNet: B=500000, D=128, L=4.   xl_L = alpha_L * x0 + beta_L
//   d_l = w_l·x0 ; alpha_{l+1} = alpha_l*(1+d_l) + c_l ; c_l = w_l·beta_l
//
// R5: 8 lanes per row, 4 rows per warp. Dot reduction = 3-step butterfly
// (offsets 1,2,4) and each warp-wide SHFL serves 4 rows simultaneously:
// 3 SHFL/row vs 20 in R3. Column assignment is strided per lane (lane li,
// chunk i -> float4 index i*8+li) so every LDG/STG instruction covers
// 4 contiguous 128B line-segments (one per row) = ideal wavefronts.
// Weights/biases live in registers, amortized over 32 rows per warp.

#define CN_L  4
#define CN_D  128
#define GPI   8    // row-groups (of 4 rows) per warp -> 32 rows/warp

__device__ __forceinline__ float red8(float v) {
#pragma unroll
    for (int off = 1; off < 8; off <<= 1)
        v += __shfl_xor_sync(0xffffffffu, v, off);
    return v;
}

__global__ __launch_bounds__(256, 1) void crossnet_kernel(
    const float4* __restrict__ x,     // inputs  [B,128] as float4 [B,32]
    const float*  __restrict__ w,     // kernels [L,128]
    const float*  __restrict__ b,     // biases  [L,128]
    float4*       __restrict__ out,
    int B)
{
    const int warp = (blockIdx.x * blockDim.x + threadIdx.x) >> 5;
    const int lane = threadIdx.x & 31;
    const int sub  = lane >> 3;     // row within group (0..3)
    const int li   = lane & 7;      // lane within 8-lane row team

    const long long g0 = (long long)warp * GPI;   // first row-group
    const long long nGroups = ((long long)B + 3) >> 2;
    if (g0 >= nGroups) return;

    const float4* w4 = reinterpret_cast<const float4*>(w);
    const float4* b4 = reinterpret_cast<const float4*>(b);

    // ---- prologue: weights (lane's 16 strided cols), beta prefix, c_l ----
    float4 wv[CN_L][4];
#pragma unroll
    for (int l = 0; l < CN_L; ++l)
#pragma unroll
        for (int i = 0; i < 4; ++i)
            wv[l][i] = __ldg(&w4[l * 32 + i * 8 + li]);

    float4 bt[4];
#pragma unroll
    for (int i = 0; i < 4; ++i) bt[i] = make_float4(0.f, 0.f, 0.f, 0.f);

    float c[CN_L];
#pragma unroll
    for (int l = 0; l < CN_L; ++l) {
        float p = 0.f;
#pragma unroll
        for (int i = 0; i < 4; ++i) {
            p = fmaf(wv[l][i].x, bt[i].x, p);
            p = fmaf(wv[l][i].y, bt[i].y, p);
            p = fmaf(wv[l][i].z, bt[i].z, p);
            p = fmaf(wv[l][i].w, bt[i].w, p);
        }
        c[l] = red8(p);                 // full dot: 8-lane team spans all 128
        float4 bl = __ldg(&b4[l * 32 + li * 4 + 0]); // dummy-avoid: see below
        // NOTE: bias layout must match weight layout (strided chunks):
        bl = __ldg(&b4[l * 32 + 0 * 8 + li]);
        bt[0].x += bl.x; bt[0].y += bl.y; bt[0].z += bl.z; bt[0].w += bl.w;
        bl = __ldg(&b4[l * 32 + 1 * 8 + li]);
        bt[1].x += bl.x; bt[1].y += bl.y; bt[1].z += bl.z; bt[1].w += bl.w;
        bl = __ldg(&b4[l * 32 + 2 * 8 + li]);
        bt[2].x += bl.x; bt[2].y += bl.y; bt[2].z += bl.z; bt[2].w += bl.w;
        bl = __ldg(&b4[l * 32 + 3 * 8 + li]);
        bt[3].x += bl.x; bt[3].y += bl.y; bt[3].z += bl.z; bt[3].w += bl.w;
    }

    // ---- main loop: 2 row-groups (8 rows) per body, loads front-batched ----
#pragma unroll
    for (int g = 0; g < GPI; g += 2) {
        const long long gA = g0 + g;
        const long long gB = gA + 1;
        const long long rowA = gA * 4 + sub;
        const long long rowB = gB * 4 + sub;
        const bool okA = (gA < nGroups) && (rowA < B);
        const bool okB = (gB < nGroups) && (rowB < B);

        float4 xa[4], xb[4];
#pragma unroll
        for (int i = 0; i < 4; ++i)
            xa[i] = okA ? __ldcs(&x[rowA * 32 + i * 8 + li])
                        : make_float4(0.f, 0.f, 0.f, 0.f);
#pragma unroll
        for (int i = 0; i < 4; ++i)
            xb[i] = okB ? __ldcs(&x[rowB * 32 + i * 8 + li])
                        : make_float4(0.f, 0.f, 0.f, 0.f);

        // partial dots d_l = w_l · x0 over this lane's 16 cols
        float pa[CN_L], pb[CN_L];
#pragma unroll
        for (int l = 0; l < CN_L; ++l) {
            float qa = 0.f, qb = 0.f;
#pragma unroll
            for (int i = 0; i < 4; ++i) {
                qa = fmaf(wv[l][i].x, xa[i].x, qa);
                qb = fmaf(wv[l][i].x, xb[i].x, qb);
                qa = fmaf(wv[l][i].y, xa[i].y, qa);
                qb = fmaf(wv[l][i].y, xb[i].y, qb);
                qa = fmaf(wv[l][i].z, xa[i].z, qa);
                qb = fmaf(wv[l][i].z, xb[i].z, qb);
                qa = fmaf(wv[l][i].w, xa[i].w, qa);
                qb = fmaf(wv[l][i].w, xb[i].w, qb);
            }
            pa[l] = qa; pb[l] = qb;
        }
        // 3-step butterfly within 8-lane teams; 8 interleaved chains
#pragma unroll
        for (int off = 1; off < 8; off <<= 1) {
#pragma unroll
            for (int l = 0; l < CN_L; ++l) {
                pa[l] += __shfl_xor_sync(0xffffffffu, pa[l], off);
                pb[l] += __shfl_xor_sync(0xffffffffu, pb[l], off);
            }
        }

        // scalar alpha recurrences
        float aA = 1.0f, aB = 1.0f;
#pragma unroll
        for (int l = 0; l < CN_L; ++l) {
            aA = fmaf(aA, pa[l], aA + c[l]);
            aB = fmaf(aB, pb[l], aB + c[l]);
        }

        if (okA) {
#pragma unroll
            for (int i = 0; i < 4; ++i) {
                float4 o;
                o.x = fmaf(xa[i].x, aA, bt[i].x);
                o.y = fmaf(xa[i].y, aA, bt[i].y);
                o.z = fmaf(xa[i].z, aA, bt[i].z);
                o.w = fmaf(xa[i].w, aA, bt[i].w);
                __stcs(&out[rowA * 32 + i * 8 + li], o);
            }
        }
        if (okB) {
#pragma unroll
            for (int i = 0; i < 4; ++i) {
                float4 o;
                o.x = fmaf(xb[i].x, aB, bt[i].x);
                o.y = fmaf(xb[i].y, aB, bt[i].y);
                o.z = fmaf(xb[i].z, aB, bt[i].z);
                o.w = fmaf(xb[i].w, aB, bt[i].w);
                __stcs(&out[rowB * 32 + i * 8 + li], o);
            }
        }
    }
}

extern "C" void kernel_launch(void* const* d_in, const int* in_sizes, int n_in,
                              void* d_out, int out_size)
{
    const float* x = (const float*)d_in[0];   // inputs  [B,128]
    const float* w = (const float*)d_in[1];   // kernels [L,128,1]
    const float* b = (const float*)d_in[2];   // biases  [L,128,1]
    float* out = (float*)d_out;

    const int B = in_sizes[0] / CN_D;                       // 500000
    const long long nGroups = ((long long)B + 3) >> 2;      // 125000
    const long long warps_needed = (nGroups + GPI - 1) / GPI;  // 15625
    const int warps_per_block = 256 / 32;
    const int grid = (int)((warps_needed + warps_per_block - 1) / warps_per_block);

    crossnet_kernel<<<grid, 256>>>(
        reinterpret_cast<const float4*>(x), w, b,
        reinterpret_cast<float4*>(out), B);
}

// round 6
// speedup vs baseline: 1.1450x; 1.1450x over previous
#include <cuda_runtime.h>
#include <cuda_bf16.h>

// CrossNet: B=500000, D=128, L=4.   out = alpha_L * x0 + beta_L
//   d_l = w_l·x0 ; alpha_{l+1} = alpha_l*(1+d_l) + c_l ; c_l = w_l·beta_l
//
// R6: 16 lanes per row, 2 rows per warp-group. 4-level butterfly reduction,
// each warp-wide SHFL serves 2 rows -> 8 SHFL/row (R3: 20). Constant state is
// 44 regs (R5's 8-lane layout needed 84 and killed occupancy). 8 rows/warp in
// two 4-row chunks, outer loop NOT unrolled to bound register pressure;
// __launch_bounds__(256,3) targets 3 blocks/SM (~37% occ).

#define CN_L  4
#define CN_D  128

__global__ __launch_bounds__(256, 3) void crossnet_kernel(
    const float4* __restrict__ x,     // inputs  [B,128] as float4 [B,32]
    const float*  __restrict__ w,     // kernels [L,128]
    const float*  __restrict__ b,     // biases  [L,128]
    float4*       __restrict__ out,
    int B)
{
    const int warp = (blockIdx.x * blockDim.x + threadIdx.x) >> 5;
    const int lane = threadIdx.x & 31;
    const int sub  = lane >> 4;     // which of the warp's 2 concurrent rows
    const int li   = lane & 15;     // lane within 16-lane row team

    const long long row0 = (long long)warp * 8;   // 8 rows per warp
    if (row0 >= B) return;

    const float4* w4 = reinterpret_cast<const float4*>(w);
    const float4* b4 = reinterpret_cast<const float4*>(b);

    // ---- prologue: lane's 8 cols per layer (2 float4), beta prefix, c_l ----
    float4 wv[CN_L][2];
#pragma unroll
    for (int l = 0; l < CN_L; ++l) {
        wv[l][0] = __ldg(&w4[l * 32 + li]);
        wv[l][1] = __ldg(&w4[l * 32 + 16 + li]);
    }

    float4 bt[2];
    bt[0] = make_float4(0.f, 0.f, 0.f, 0.f);
    bt[1] = make_float4(0.f, 0.f, 0.f, 0.f);

    float c[CN_L];
#pragma unroll
    for (int l = 0; l < CN_L; ++l) {
        float p = 0.f;
#pragma unroll
        for (int h = 0; h < 2; ++h) {
            p = fmaf(wv[l][h].x, bt[h].x, p);
            p = fmaf(wv[l][h].y, bt[h].y, p);
            p = fmaf(wv[l][h].z, bt[h].z, p);
            p = fmaf(wv[l][h].w, bt[h].w, p);
        }
#pragma unroll
        for (int off = 1; off < 16; off <<= 1)
            p += __shfl_xor_sync(0xffffffffu, p, off);
        c[l] = p;
        float4 bl0 = __ldg(&b4[l * 32 + li]);
        float4 bl1 = __ldg(&b4[l * 32 + 16 + li]);
        bt[0].x += bl0.x; bt[0].y += bl0.y; bt[0].z += bl0.z; bt[0].w += bl0.w;
        bt[1].x += bl1.x; bt[1].y += bl1.y; bt[1].z += bl1.z; bt[1].w += bl1.w;
    }

    // ---- main: 2 chunks of 4 rows (2 groups x 2 rows) ----
#pragma unroll 1
    for (int chunk = 0; chunk < 2; ++chunk) {
        const long long rA = row0 + chunk * 4 + sub;        // group 0 row
        const long long rB = row0 + chunk * 4 + 2 + sub;    // group 1 row
        const bool okA = rA < B;
        const bool okB = rB < B;

        // 4 independent LDG.128 per lane, front-batched
        float4 xa[2], xb[2];
        xa[0] = okA ? __ldcs(&x[rA * 32 + li])      : make_float4(0,0,0,0);
        xa[1] = okA ? __ldcs(&x[rA * 32 + 16 + li]) : make_float4(0,0,0,0);
        xb[0] = okB ? __ldcs(&x[rB * 32 + li])      : make_float4(0,0,0,0);
        xb[1] = okB ? __ldcs(&x[rB * 32 + 16 + li]) : make_float4(0,0,0,0);

        // partial dots d_l = w_l · x0 over this lane's 8 cols
        float pa[CN_L], pb[CN_L];
#pragma unroll
        for (int l = 0; l < CN_L; ++l) {
            float qa = 0.f, qb = 0.f;
#pragma unroll
            for (int h = 0; h < 2; ++h) {
                qa = fmaf(wv[l][h].x, xa[h].x, qa);
                qb = fmaf(wv[l][h].x, xb[h].x, qb);
                qa = fmaf(wv[l][h].y, xa[h].y, qa);
                qb = fmaf(wv[l][h].y, xb[h].y, qb);
                qa = fmaf(wv[l][h].z, xa[h].z, qa);
                qb = fmaf(wv[l][h].z, xb[h].z, qb);
                qa = fmaf(wv[l][h].w, xa[h].w, qa);
                qb = fmaf(wv[l][h].w, xb[h].w, qb);
            }
            pa[l] = qa; pb[l] = qb;
        }
        // 4-level butterfly within 16-lane teams; 8 interleaved chains,
        // each SHFL instruction reduces both sub-rows at once.
#pragma unroll
        for (int off = 1; off < 16; off <<= 1) {
#pragma unroll
            for (int l = 0; l < CN_L; ++l) {
                pa[l] += __shfl_xor_sync(0xffffffffu, pa[l], off);
                pb[l] += __shfl_xor_sync(0xffffffffu, pb[l], off);
            }
        }

        // scalar alpha recurrences
        float aA = 1.0f, aB = 1.0f;
#pragma unroll
        for (int l = 0; l < CN_L; ++l) {
            aA = fmaf(aA, pa[l], aA + c[l]);
            aB = fmaf(aB, pb[l], aB + c[l]);
        }

        if (okA) {
            float4 o;
            o.x = fmaf(xa[0].x, aA, bt[0].x);
            o.y = fmaf(xa[0].y, aA, bt[0].y);
            o.z = fmaf(xa[0].z, aA, bt[0].z);
            o.w = fmaf(xa[0].w, aA, bt[0].w);
            __stcs(&out[rA * 32 + li], o);
            o.x = fmaf(xa[1].x, aA, bt[1].x);
            o.y = fmaf(xa[1].y, aA, bt[1].y);
            o.z = fmaf(xa[1].z, aA, bt[1].z);
            o.w = fmaf(xa[1].w, aA, bt[1].w);
            __stcs(&out[rA * 32 + 16 + li], o);
        }
        if (okB) {
            float4 o;
            o.x = fmaf(xb[0].x, aB, bt[0].x);
            o.y = fmaf(xb[0].y, aB, bt[0].y);
            o.z = fmaf(xb[0].z, aB, bt[0].z);
            o.w = fmaf(xb[0].w, aB, bt[0].w);
            __stcs(&out[rB * 32 + li], o);
            o.x = fmaf(xb[1].x, aB, bt[1].x);
            o.y = fmaf(xb[1].y, aB, bt[1].y);
            o.z = fmaf(xb[1].z, aB, bt[1].z);
            o.w = fmaf(xb[1].w, aB, bt[1].w);
            __stcs(&out[rB * 32 + 16 + li], o);
        }
    }
}

extern "C" void kernel_launch(void* const* d_in, const int* in_sizes, int n_in,
                              void* d_out, int out_size)
{
    const float* x = (const float*)d_in[0];   // inputs  [B,128]
    const float* w = (const float*)d_in[1];   // kernels [L,128,1]
    const float* b = (const float*)d_in[2];   // biases  [L,128,1]
    float* out = (float*)d_out;

    const int B = in_sizes[0] / CN_D;                     // 500000
    const long long warps_needed = ((long long)B + 7) / 8;   // 62500
    const int warps_per_block = 256 / 32;
    const int grid = (int)((warps_needed + warps_per_block - 1) / warps_per_block);

    crossnet_kernel<<<grid, 256>>>(
        reinterpret_cast<const float4*>(x), w, b,
        reinterpret_cast<float4*>(out), B);
}

// round 7
// speedup vs baseline: 1.2030x; 1.0506x over previous
#include <cuda_runtime.h>
#include <cuda_bf16.h>

// CrossNet: B=500000, D=128, L=4.   out = alpha_L * x0 + beta_L
//   d_l = w_l·x0 ; alpha_{l+1} = alpha_l*(1+d_l) + c_l ; c_l = w_l·beta_l
//
// R7: same 16-lane-team layout as R6 (8 SHFL/row), but weights live in SMEM
// (2KB, staged once per block) instead of 32 persistent registers. With
// __launch_bounds__(256,4) the kernel fits 64 regs -> 4 blocks/SM (50% occ)
// instead of 3 (R6: 80 regs, 31% occ, DRAM stuck at 72% = latency-bound).

#define CN_L  4
#define CN_D  128

__global__ __launch_bounds__(256, 4) void crossnet_kernel(
    const float4* __restrict__ x,     // inputs  [B,128] as float4 [B,32]
    const float4* __restrict__ w4,    // kernels [L,128] as float4 [L,32]
    const float4* __restrict__ b4,    // biases
    float4*       __restrict__ out,
    int B)
{
    __shared__ float4 ws[CN_L * 32];  // weights, global layout mirrored

    const int tid  = threadIdx.x;
    // stage weights into smem (one pass, 128 float4s, 256 threads)
    if (tid < CN_L * 32) ws[tid] = w4[tid];
    __syncthreads();

    const int warp = (blockIdx.x * blockDim.x + tid) >> 5;
    const int lane = tid & 31;
    const int sub  = lane >> 4;     // which of the warp's 2 concurrent rows
    const int li   = lane & 15;     // lane within 16-lane row team

    const long long row0 = (long long)warp * 8;   // 8 rows per warp
    if (row0 >= B) return;

    // ---- prologue: beta prefix + c_l (biases via L1-resident LDG) ----
    float4 bt0 = make_float4(0.f, 0.f, 0.f, 0.f);
    float4 bt1 = make_float4(0.f, 0.f, 0.f, 0.f);
    float c[CN_L];
#pragma unroll
    for (int l = 0; l < CN_L; ++l) {
        const float4 w0 = ws[l * 32 + li];
        const float4 w1 = ws[l * 32 + 16 + li];
        float p = 0.f;
        p = fmaf(w0.x, bt0.x, p); p = fmaf(w0.y, bt0.y, p);
        p = fmaf(w0.z, bt0.z, p); p = fmaf(w0.w, bt0.w, p);
        p = fmaf(w1.x, bt1.x, p); p = fmaf(w1.y, bt1.y, p);
        p = fmaf(w1.z, bt1.z, p); p = fmaf(w1.w, bt1.w, p);
#pragma unroll
        for (int off = 1; off < 16; off <<= 1)
            p += __shfl_xor_sync(0xffffffffu, p, off);
        c[l] = p;
        const float4 bl0 = __ldg(&b4[l * 32 + li]);
        const float4 bl1 = __ldg(&b4[l * 32 + 16 + li]);
        bt0.x += bl0.x; bt0.y += bl0.y; bt0.z += bl0.z; bt0.w += bl0.w;
        bt1.x += bl1.x; bt1.y += bl1.y; bt1.z += bl1.z; bt1.w += bl1.w;
    }

    // ---- main: 2 chunks of 4 rows (2 groups x 2 sub-rows) ----
#pragma unroll 1
    for (int chunk = 0; chunk < 2; ++chunk) {
        const long long rA = row0 + chunk * 4 + sub;
        const long long rB = row0 + chunk * 4 + 2 + sub;
        const bool okA = rA < B;
        const bool okB = rB < B;

        // 4 independent LDG.128 per lane, front-batched
        float4 xa0 = okA ? __ldcs(&x[rA * 32 + li])      : make_float4(0,0,0,0);
        float4 xa1 = okA ? __ldcs(&x[rA * 32 + 16 + li]) : make_float4(0,0,0,0);
        float4 xb0 = okB ? __ldcs(&x[rB * 32 + li])      : make_float4(0,0,0,0);
        float4 xb1 = okB ? __ldcs(&x[rB * 32 + 16 + li]) : make_float4(0,0,0,0);

        // partial dots d_l = w_l · x0 ; weights streamed from smem per layer
        float pa[CN_L], pb[CN_L];
#pragma unroll
        for (int l = 0; l < CN_L; ++l) {
            const float4 w0 = ws[l * 32 + li];
            const float4 w1 = ws[l * 32 + 16 + li];
            float qa = 0.f, qb = 0.f;
            qa = fmaf(w0.x, xa0.x, qa);  qb = fmaf(w0.x, xb0.x, qb);
            qa = fmaf(w0.y, xa0.y, qa);  qb = fmaf(w0.y, xb0.y, qb);
            qa = fmaf(w0.z, xa0.z, qa);  qb = fmaf(w0.z, xb0.z, qb);
            qa = fmaf(w0.w, xa0.w, qa);  qb = fmaf(w0.w, xb0.w, qb);
            qa = fmaf(w1.x, xa1.x, qa);  qb = fmaf(w1.x, xb1.x, qb);
            qa = fmaf(w1.y, xa1.y, qa);  qb = fmaf(w1.y, xb1.y, qb);
            qa = fmaf(w1.z, xa1.z, qa);  qb = fmaf(w1.z, xb1.z, qb);
            qa = fmaf(w1.w, xa1.w, qa);  qb = fmaf(w1.w, xb1.w, qb);
            pa[l] = qa; pb[l] = qb;
        }
        // 4-level butterfly within 16-lane teams; 8 interleaved chains
#pragma unroll
        for (int off = 1; off < 16; off <<= 1) {
#pragma unroll
            for (int l = 0; l < CN_L; ++l) {
                pa[l] += __shfl_xor_sync(0xffffffffu, pa[l], off);
                pb[l] += __shfl_xor_sync(0xffffffffu, pb[l], off);
            }
        }

        // scalar alpha recurrences
        float aA = 1.0f, aB = 1.0f;
#pragma unroll
        for (int l = 0; l < CN_L; ++l) {
            aA = fmaf(aA, pa[l], aA + c[l]);
            aB = fmaf(aB, pb[l], aB + c[l]);
        }

        if (okA) {
            float4 o;
            o.x = fmaf(xa0.x, aA, bt0.x); o.y = fmaf(xa0.y, aA, bt0.y);
            o.z = fmaf(xa0.z, aA, bt0.z); o.w = fmaf(xa0.w, aA, bt0.w);
            __stcs(&out[rA * 32 + li], o);
            o.x = fmaf(xa1.x, aA, bt1.x); o.y = fmaf(xa1.y, aA, bt1.y);
            o.z = fmaf(xa1.z, aA, bt1.z); o.w = fmaf(xa1.w, aA, bt1.w);
            __stcs(&out[rA * 32 + 16 + li], o);
        }
        if (okB) {
            float4 o;
            o.x = fmaf(xb0.x, aB, bt0.x); o.y = fmaf(xb0.y, aB, bt0.y);
            o.z = fmaf(xb0.z, aB, bt0.z); o.w = fmaf(xb0.w, aB, bt0.w);
            __stcs(&out[rB * 32 + li], o);
            o.x = fmaf(xb1.x, aB, bt1.x); o.y = fmaf(xb1.y, aB, bt1.y);
            o.z = fmaf(xb1.z, aB, bt1.z); o.w = fmaf(xb1.w, aB, bt1.w);
            __stcs(&out[rB * 32 + 16 + li], o);
        }
    }
}

extern "C" void kernel_launch(void* const* d_in, const int* in_sizes, int n_in,
                              void* d_out, int out_size)
{
    const float* x = (const float*)d_in[0];   // inputs  [B,128]
    const float* w = (const float*)d_in[1];   // kernels [L,128,1]
    const float* b = (const float*)d_in[2];   // biases  [L,128,1]
    float* out = (float*)d_out;

    const int B = in_sizes[0] / CN_D;                       // 500000
    const long long warps_needed = ((long long)B + 7) / 8;  // 62500
    const int warps_per_block = 256 / 32;
    const int grid = (int)((warps_needed + warps_per_block - 1) / warps_per_block);

    crossnet_kernel<<<grid, 256>>>(
        reinterpret_cast<const float4*>(x),
        reinterpret_cast<const float4*>(w),
        reinterpret_cast<const float4*>(b),
        reinterpret_cast<float4*>(out), B);
}